// round 11
// baseline (speedup 1.0000x reference)
#include <cuda_runtime.h>
#include <cuda_fp16.h>
#include <cstdint>

// ---------------- constants ----------------
#define NMAX 50048
#define ETHREADS 256
#define EGRID 152
#define KSE 280     // edge A/W k-stride in halves (560B rows: ldmatrix conflict-free)
#define KSN 104     // node W k-stride in halves (208B rows: conflict-free)

// ---------------- device scratch ----------------
__device__ __align__(16) float g_Q[NMAX * 12];
__device__ __align__(16) __half g_WE[128 * KSE];   // fp16 edge_W [j][k]
__device__ __align__(16) __half g_WN[128 * KSN];   // fp16 node_W [j][k]

__constant__ int c_EPA[16] = {1,1,2,1,0,1,3,2,2,0,2,3,0,0,3,3};
__constant__ int c_EPB[16] = {1,2,1,0,1,3,1,2,0,2,3,2,0,3,0,3};
__constant__ int c_NPA[6]  = {1,1,1,0,0,3};
__constant__ int c_NPB[6]  = {0,2,3,2,3,2};
__constant__ int c_DSEL[4] = {1,0,2,3};

// ---------------- PTX helpers (baseline ISA only) ----------------
__device__ __forceinline__ uint32_t smem_u32(const void* p) {
    uint32_t a;
    asm("{ .reg .u64 t; cvta.to.shared.u64 t, %1; cvt.u32.u64 %0, t; }" : "=r"(a) : "l"(p));
    return a;
}
__device__ __forceinline__ void ldsm4(uint32_t& r0, uint32_t& r1, uint32_t& r2, uint32_t& r3, uint32_t a) {
    asm volatile("ldmatrix.sync.aligned.m8n8.x4.shared.b16 {%0,%1,%2,%3}, [%4];"
        : "=r"(r0), "=r"(r1), "=r"(r2), "=r"(r3) : "r"(a));
}
#define MMA16816(c, a0,a1,a2,a3, b0,b1) \
    asm volatile("mma.sync.aligned.m16n8k16.row.col.f32.f16.f16.f32 " \
        "{%0,%1,%2,%3}, {%4,%5,%6,%7}, {%8,%9}, {%0,%1,%2,%3};" \
        : "+f"((c)[0]), "+f"((c)[1]), "+f"((c)[2]), "+f"((c)[3]) \
        : "r"(a0), "r"(a1), "r"(a2), "r"(a3), "r"(b0), "r"(b1))

// ---------------- SMEM layout (bytes) ----------------
#define WE_OFF  0
#define WN_OFF  (WE_OFF + 128 * KSE * 2)        // 71680
#define A_OFF   (WN_OFF + 128 * KSN * 2)        // 98304
#define XS_OFF  (A_OFF + 128 * KSE * 2)         // 169984
#define XD_OFF  (XS_OFF + 6144)
#define Q_OFF   (XD_OFF + 6144)
#define SD_OFF  (Q_OFF + 6144)
#define IDX_OFF (SD_OFF + 8192)
#define LN_OFF  (IDX_OFF + 1024)
#define EB_OFF  (LN_OFF + 2048)
#define GE_OFF  (EB_OFF + 512)
#define BE_OFF  (GE_OFF + 512)
#define NB_OFF  (BE_OFF + 512)
#define GN_OFF  (NB_OFF + 512)
#define BN_OFF  (GN_OFF + 512)
#define SMEM_T  (BN_OFF + 512)

// ---------------- small math ----------------
struct F3 { float x, y, z; };
__device__ __forceinline__ F3 f3sub(F3 a, F3 b) { return {a.x-b.x, a.y-b.y, a.z-b.z}; }
__device__ __forceinline__ F3 f3cross(F3 a, F3 b) {
    return {a.y*b.z - a.z*b.y, a.z*b.x - a.x*b.z, a.x*b.y - a.y*b.x};
}
__device__ __forceinline__ F3 f3nrm(F3 v) {
    float n = sqrtf(v.x*v.x + v.y*v.y + v.z*v.z);
    if (n == 0.0f) n = 1.0f;
    float i = 1.0f / n;
    return {v.x*i, v.y*i, v.z*i};
}

// ---------------- prep kernels ----------------
__global__ void wprepE_kernel(const float* __restrict__ eW) {
    int idx = blockIdx.x * 256 + threadIdx.x;
    if (idx >= 128 * KSE) return;
    int j = idx / KSE, k = idx - j * KSE;
    g_WE[idx] = __float2half_rn((k < 268) ? eW[j * 268 + k] : 0.0f);
}
__global__ void wprepN_kernel(const float* __restrict__ nW) {
    int idx = blockIdx.x * 256 + threadIdx.x;
    if (idx >= 128 * KSN) return;
    int j = idx / KSN, k = idx - j * KSN;
    g_WN[idx] = __float2half_rn((k < 96) ? nW[j * 96 + k] : 0.0f);
}
__global__ void q_kernel(const float* __restrict__ X, int N) {
    int n = blockIdx.x * blockDim.x + threadIdx.x;
    if (n >= N) return;
    float4* Qo = ((float4*)g_Q) + (size_t)n * 3;
    if (n == N - 1) {
        float4 z = make_float4(0.f, 0.f, 0.f, 0.f);
        Qo[0] = z; Qo[1] = z; Qo[2] = z;
        return;
    }
    const float* x = X + (size_t)n * 12;
    F3 X0 = {x[0], x[1], x[2]};
    F3 X1 = {x[3], x[4], x[5]};
    F3 X2 = {x[6], x[7], x[8]};
    F3 u0 = f3nrm(f3sub(X1, X0));
    F3 u1 = f3nrm(f3sub(X2, X1));
    F3 n0 = f3nrm(f3cross(u0, u1));
    F3 b1 = f3nrm(f3sub(u0, u1));
    F3 cc = f3cross(b1, n0);
    Qo[0] = make_float4(b1.x, n0.x, cc.x, 0.f);
    Qo[1] = make_float4(b1.y, n0.y, cc.y, 0.f);
    Qo[2] = make_float4(b1.z, n0.z, cc.z, 0.f);
}

// ---------------- MMA (2x4 warp tiling) + LN + store ----------------
// Warp (we = w&3, wj = w>>2): rows we*32..+31, cols wj*64..+63.
// aRstep: A row-group step (ALWAYS KSE-based — A is stored at KSE stride).
// bRstep: B row-group step (KSE or KSN depending on which W).
__device__ __forceinline__ void mma_ln_store(
    char* sm, uint32_t aBase, uint32_t bBase, uint32_t aRstep, uint32_t bRstep, int S,
    int we, int wj, int lane,
    const float* sEB, const float* sGE, const float* sBE,
    float* __restrict__ outp, int rowbase, int rowlim)
{
    float acc[64];
#pragma unroll
    for (int i = 0; i < 64; i++) acc[i] = 0.f;

#pragma unroll 1
    for (int s = 0; s < S; s++) {
        uint32_t koff = (uint32_t)(s << 5);   // 16 halves = 32 bytes
        uint32_t a0, a1, a2, a3, a4, a5, a6, a7;
        ldsm4(a0, a1, a2, a3, aBase + koff);
        ldsm4(a4, a5, a6, a7, aBase + aRstep + koff);
#pragma unroll
        for (int bq = 0; bq < 4; bq++) {
            uint32_t b0, b1, b2, b3;
            ldsm4(b0, b1, b2, b3, bBase + koff + (uint32_t)bq * bRstep);
            MMA16816(&acc[(bq*2    ) * 4],      a0, a1, a2, a3, b0, b2);
            MMA16816(&acc[(bq*2 + 1) * 4],      a0, a1, a2, a3, b1, b3);
            MMA16816(&acc[32 + (bq*2    ) * 4], a4, a5, a6, a7, b0, b2);
            MMA16816(&acc[32 + (bq*2 + 1) * 4], a4, a5, a6, a7, b1, b3);
        }
    }

    // epilogue: bias + partial LN over this warp's 64 cols, exchange with paired warp (wj^1)
    float2* sLN = (float2*)(sm + LN_OFF);
    int rlo = lane >> 2, q2 = (lane & 3) << 1;
    int jbase = (wj << 6) + q2;
    float ps1[4], ps2[4];
#pragma unroll
    for (int af = 0; af < 2; af++)
#pragma unroll
        for (int hi = 0; hi < 2; hi++) {
            float s1 = 0.f, s2 = 0.f;
#pragma unroll
            for (int nb = 0; nb < 8; nb++) {
                int j = jbase + (nb << 3);
                int ai = af*32 + nb*4 + hi*2;
                float v0 = acc[ai]     + sEB[j];
                float v1 = acc[ai + 1] + sEB[j + 1];
                acc[ai]     = v0;
                acc[ai + 1] = v1;
                s1 += v0 + v1;
                s2 += v0*v0 + v1*v1;
            }
            s1 += __shfl_xor_sync(0xffffffffu, s1, 1);
            s2 += __shfl_xor_sync(0xffffffffu, s2, 1);
            s1 += __shfl_xor_sync(0xffffffffu, s1, 2);
            s2 += __shfl_xor_sync(0xffffffffu, s2, 2);
            int rl = (we << 5) + (af << 4) + (hi << 3) + rlo;
            if ((lane & 3) == 0) sLN[(wj << 7) + rl] = make_float2(s1, s2);
            ps1[af*2 + hi] = s1;
            ps2[af*2 + hi] = s2;
        }
    __syncthreads();
#pragma unroll
    for (int af = 0; af < 2; af++)
#pragma unroll
        for (int hi = 0; hi < 2; hi++) {
            int rl = (we << 5) + (af << 4) + (hi << 3) + rlo;
            float2 o = sLN[((wj ^ 1) << 7) + rl];
            float S1 = ps1[af*2 + hi] + o.x;
            float S2 = ps2[af*2 + hi] + o.y;
            float mean = S1 * (1.f/128.f);
            float var  = (S2 - S1 * mean) * (1.f/127.f);
            float inv  = 1.f / (sqrtf(var + 1e-6f) + 1e-6f);
            int row = rowbase + rl;
            if (row < rowlim) {
                float* op = outp + (size_t)row * 128;
#pragma unroll
                for (int nb = 0; nb < 8; nb++) {
                    int j = jbase + (nb << 3);
                    int ai = af*32 + nb*4 + hi*2;
                    float2 ov;
                    ov.x = sGE[j]     * (acc[ai]     - mean) * inv + sBE[j];
                    ov.y = sGE[j + 1] * (acc[ai + 1] - mean) * inv + sBE[j + 1];
                    *(float2*)(op + j) = ov;
                }
            }
        }
}

// ---------------- fused persistent kernel: edge tiles + node tiles ----------------
__global__ __launch_bounds__(ETHREADS, 1) void fused_kernel(
    const float* __restrict__ X,
    const int* __restrict__ inS, const int* __restrict__ inD,
    const int* __restrict__ exS, const int* __restrict__ exD,
    const float* __restrict__ nb_, const float* __restrict__ gn, const float* __restrict__ bn,
    const float* __restrict__ eb, const float* __restrict__ ge, const float* __restrict__ be,
    float* __restrict__ out, int N, int E)
{
    extern __shared__ char sm[];
    uint32_t smb = smem_u32(sm);
    int tid = threadIdx.x;
    int w = tid >> 5, lane = tid & 31;

    __half* Ah = (__half*)(sm + A_OFF);

    // one-time: weights + params into SMEM
    for (int i = tid; i < 128 * KSE / 8; i += ETHREADS)
        ((uint4*)(sm + WE_OFF))[i] = ((const uint4*)g_WE)[i];
    for (int i = tid; i < 128 * KSN / 8; i += ETHREADS)
        ((uint4*)(sm + WN_OFF))[i] = ((const uint4*)g_WN)[i];
    if (tid < 128) {
        ((float*)(sm + EB_OFF))[tid] = eb[tid];
        ((float*)(sm + GE_OFF))[tid] = ge[tid];
        ((float*)(sm + BE_OFF))[tid] = be[tid];
        ((float*)(sm + NB_OFF))[tid] = nb_[tid];
        ((float*)(sm + GN_OFF))[tid] = gn[tid];
        ((float*)(sm + BN_OFF))[tid] = bn[tid];
        *(unsigned long long*)(Ah + tid * KSE + 268) = 0ull;   // zero-pad k=268..271 once
    }
    __syncthreads();

    float* sXs = (float*)(sm + XS_OFF);
    float* sXd = (float*)(sm + XD_OFF);
    float* sQ  = (float*)(sm + Q_OFF);
    float* sD  = (float*)(sm + SD_OFF);
    int*   sIdx = (int*)(sm + IDX_OFF);

    // ldmatrix lane address components; 2x4 warp tiling
    int we = w & 3, wj = w >> 2;
    int lm = lane >> 3, lr = lane & 7;
    uint32_t rowsel = (uint32_t)(((lm & 1) << 3) + lr);
    uint32_t colByte = (uint32_t)((lm >> 1) << 4);
    uint32_t aBase  = smb + A_OFF  + ((uint32_t)(we << 5) + rowsel) * (KSE * 2u) + colByte;
    uint32_t bBaseE = smb + WE_OFF + ((uint32_t)(wj << 6) + rowsel) * (KSE * 2u) + colByte;
    uint32_t bBaseN = smb + WN_OFF + ((uint32_t)(wj << 6) + rowsel) * (KSN * 2u) + colByte;
    const uint32_t aRstep = (KSE * 2u) << 4;   // A always stored at KSE stride
    const uint32_t bRstepE = (KSE * 2u) << 4;
    const uint32_t bRstepN = (KSN * 2u) << 4;

    float* outIn = out + (size_t)N * 128;
    float* outEx = outIn + (size_t)E * 128;

    int ntE = (E + 127) >> 7;
    int ntN = (N + 127) >> 7;
    int ntot = 2 * ntE + ntN;

    for (int t = blockIdx.x; t < ntot; t += gridDim.x) {
        if (t < 2 * ntE) {
            // ================= EDGE TILE =================
            int set = (t >= ntE);
            int tl = set ? (t - ntE) : t;
            const int* srcp = set ? exS : inS;
            const int* dstp = set ? exD : inD;
            float* outp = set ? outEx : outIn;
            int base = tl << 7;

            // stage indices
            {
                int e = base + (tid & 127);
                if (e >= E) e = E - 1;
                sIdx[tid] = (tid < 128) ? srcp[e] : dstp[e];
            }
            __syncthreads();

            // gather X(src), X(dst), Q(src)
            {
                const float4* X4 = (const float4*)X;
                const float4* Q4 = (const float4*)g_Q;
                for (int i = tid; i < 384; i += ETHREADS) {
                    int e = i / 3, r = i - e * 3;
                    ((float4*)sXs)[i] = X4[(size_t)sIdx[e] * 3 + r];
                    ((float4*)sXd)[i] = X4[(size_t)sIdx[128 + e] * 3 + r];
                    ((float4*)sQ )[i] = Q4[(size_t)sIdx[e] * 3 + r];
                }
            }
            __syncthreads();

            // distances: 16 pairs x 128 edges
            for (int i = tid; i < 2048; i += ETHREADS) {
                int p = i >> 7, e = i & 127;
                int a = c_EPA[p], b = c_EPB[p];
                const float* xs = sXs + e*12 + a*3;
                const float* xd = sXd + e*12 + b*3;
                float dx = xs[0]-xd[0], dy = xs[1]-xd[1], dz = xs[2]-xd[2];
                sD[(p << 7) + e] = sqrtf(dx*dx + dy*dy + dz*dz + 1e-6f);
            }
            // direct features k=256..267
            {
                int e = tid & 127, hf = tid >> 7;
                const float* xs = sXs + e*12;
                const float* xd = sXd + e*12;
                const float* q  = sQ  + e*12;
#pragma unroll
                for (int ii = 0; ii < 2; ii++) {
                    int a = hf * 2 + ii;
                    int da = c_DSEL[a];
                    float v0 = xd[da*3+0] - xs[0];
                    float v1 = xd[da*3+1] - xs[1];
                    float v2 = xd[da*3+2] - xs[2];
                    float d0 = q[0]*v0 + q[1]*v1 + q[2]*v2;
                    float d1 = q[4]*v0 + q[5]*v1 + q[6]*v2;
                    float d2 = q[8]*v0 + q[9]*v1 + q[10]*v2;
                    float nn = sqrtf(d0*d0 + d1*d1 + d2*d2);
                    if (nn == 0.0f) nn = 1.0f;
                    float inv = 1.0f / nn;
                    int k = 256 + a * 3;
                    Ah[e * KSE + k]     = __float2half_rn(d0 * inv);
                    Ah[e * KSE + k + 1] = __float2half_rn(d1 * inv);
                    Ah[e * KSE + k + 2] = __float2half_rn(d2 * inv);
                }
            }
            __syncthreads();

            // RBF: thread (e, hf) does 8 mus for each of 16 pairs
            {
                int e = tid & 127, hf = tid >> 7;
                int r0 = hf * 8;
#pragma unroll 1
                for (int p = 0; p < 16; p++) {
                    float d = sD[(p << 7) + e];
                    uint32_t pk[4];
#pragma unroll
                    for (int j2 = 0; j2 < 4; j2++) {
                        float u0 = (d - (float)(r0 + 2*j2)     * (20.0f/15.0f)) * 0.8f;
                        float u1 = (d - (float)(r0 + 2*j2 + 1) * (20.0f/15.0f)) * 0.8f;
                        __half2 h = __floats2half2_rn(__expf(-u0*u0), __expf(-u1*u1));
                        pk[j2] = *(uint32_t*)&h;
                    }
                    *(uint4*)(Ah + e * KSE + p * 16 + r0) = make_uint4(pk[0], pk[1], pk[2], pk[3]);
                }
            }
            __syncthreads();

            mma_ln_store(sm, aBase, bBaseE, aRstep, bRstepE, 17, we, wj, lane,
                         (const float*)(sm + EB_OFF), (const float*)(sm + GE_OFF), (const float*)(sm + BE_OFF),
                         outp, base, E);
        } else {
            // ================= NODE TILE =================
            int tl = t - 2 * ntE;
            int base = tl << 7;

            // load node X directly (contiguous)
            {
                const float4* X4 = (const float4*)X;
                for (int i = tid; i < 384; i += ETHREADS) {
                    int e = i / 3, r = i - e * 3;
                    int n = base + e; if (n >= N) n = N - 1;
                    ((float4*)sXs)[i] = X4[(size_t)n * 3 + r];
                }
            }
            __syncthreads();

            // 6 intra-node distances
            for (int i = tid; i < 768; i += ETHREADS) {
                int p = i >> 7, e = i & 127;
                int a = c_NPA[p], b = c_NPB[p];
                const float* xa = sXs + e*12 + a*3;
                const float* xb = sXs + e*12 + b*3;
                float dx = xa[0]-xb[0], dy = xa[1]-xb[1], dz = xa[2]-xb[2];
                sD[(p << 7) + e] = sqrtf(dx*dx + dy*dy + dz*dz + 1e-6f);
            }
            __syncthreads();

            // RBF: 96 features (6 pairs x 16 mus) into A (KSE stride, cols 0..95)
            {
                int e = tid & 127, hf = tid >> 7;
                int r0 = hf * 8;
#pragma unroll 1
                for (int p = 0; p < 6; p++) {
                    float d = sD[(p << 7) + e];
                    uint32_t pk[4];
#pragma unroll
                    for (int j2 = 0; j2 < 4; j2++) {
                        float u0 = (d - (float)(r0 + 2*j2)     * (20.0f/15.0f)) * 0.8f;
                        float u1 = (d - (float)(r0 + 2*j2 + 1) * (20.0f/15.0f)) * 0.8f;
                        __half2 h = __floats2half2_rn(__expf(-u0*u0), __expf(-u1*u1));
                        pk[j2] = *(uint32_t*)&h;
                    }
                    *(uint4*)(Ah + e * KSE + p * 16 + r0) = make_uint4(pk[0], pk[1], pk[2], pk[3]);
                }
            }
            __syncthreads();

            mma_ln_store(sm, aBase, bBaseN, aRstep, bRstepN, 6, we, wj, lane,
                         (const float*)(sm + NB_OFF), (const float*)(sm + GN_OFF), (const float*)(sm + BN_OFF),
                         out, base, N);
        }
    }
}

// ---------------- launch ----------------
extern "C" void kernel_launch(void* const* d_in, const int* in_sizes, int n_in,
                              void* d_out, int out_size)
{
    const float* X   = (const float*)d_in[0];
    const int*   Ein = (const int*)  d_in[1];
    const int*   Eex = (const int*)  d_in[2];
    const float* nW  = (const float*)d_in[3];
    const float* nb  = (const float*)d_in[4];
    const float* eW  = (const float*)d_in[5];
    const float* eb  = (const float*)d_in[6];
    const float* gn  = (const float*)d_in[7];
    const float* bn  = (const float*)d_in[8];
    const float* ge  = (const float*)d_in[9];
    const float* be  = (const float*)d_in[10];

    int N = in_sizes[0] / 12;
    int E = in_sizes[1] / 2;
    float* out = (float*)d_out;

    cudaFuncSetAttribute(fused_kernel, cudaFuncAttributeMaxDynamicSharedMemorySize, SMEM_T);

    wprepE_kernel<<<(128*KSE + 255)/256, 256>>>(eW);
    wprepN_kernel<<<(128*KSN + 255)/256, 256>>>(nW);
    q_kernel<<<(N + 255)/256, 256>>>(X, N);

    fused_kernel<<<EGRID, ETHREADS, SMEM_T>>>(
        X, Ein, Ein + E, Eex, Eex + E,
        nb, gn, bn, eb, ge, be, out, N, E);
}

// round 12
// speedup vs baseline: 1.7967x; 1.7967x over previous
#include <cuda_runtime.h>
#include <cuda_fp16.h>
#include <cstdint>

// ---------------- constants ----------------
#define NMAX 50048
#define ETHREADS 256
#define EGRID 152
#define KSE 280     // edge A/W k-stride in halves (560B rows: ldmatrix conflict-free)
#define KSN 104     // node W k-stride in halves (208B rows: conflict-free)

// ---------------- device scratch ----------------
__device__ __align__(16) float g_Q[NMAX * 12];
__device__ __align__(16) __half g_WE[128 * KSE];   // fp16 edge_W [j][k]
__device__ __align__(16) __half g_WN[128 * KSN];   // fp16 node_W [j][k]

__constant__ int c_EPA[16] = {1,1,2,1,0,1,3,2,2,0,2,3,0,0,3,3};
__constant__ int c_EPB[16] = {1,2,1,0,1,3,1,2,0,2,3,2,0,3,0,3};
__constant__ int c_NPA[6]  = {1,1,1,0,0,3};
__constant__ int c_NPB[6]  = {0,2,3,2,3,2};
__constant__ int c_DSEL[4] = {1,0,2,3};

// ---------------- PTX helpers (baseline ISA only) ----------------
__device__ __forceinline__ uint32_t smem_u32(const void* p) {
    uint32_t a;
    asm("{ .reg .u64 t; cvta.to.shared.u64 t, %1; cvt.u32.u64 %0, t; }" : "=r"(a) : "l"(p));
    return a;
}
__device__ __forceinline__ void ldsm4(uint32_t& r0, uint32_t& r1, uint32_t& r2, uint32_t& r3, uint32_t a) {
    asm volatile("ldmatrix.sync.aligned.m8n8.x4.shared.b16 {%0,%1,%2,%3}, [%4];"
        : "=r"(r0), "=r"(r1), "=r"(r2), "=r"(r3) : "r"(a));
}
#define MMA16816(c, a0,a1,a2,a3, b0,b1) \
    asm volatile("mma.sync.aligned.m16n8k16.row.col.f32.f16.f16.f32 " \
        "{%0,%1,%2,%3}, {%4,%5,%6,%7}, {%8,%9}, {%0,%1,%2,%3};" \
        : "+f"((c)[0]), "+f"((c)[1]), "+f"((c)[2]), "+f"((c)[3]) \
        : "r"(a0), "r"(a1), "r"(a2), "r"(a3), "r"(b0), "r"(b1))

// ---------------- SMEM layout (bytes) ----------------
#define WE_OFF  0
#define WN_OFF  (WE_OFF + 128 * KSE * 2)        // 71680
#define A_OFF   (WN_OFF + 128 * KSN * 2)        // 98304
#define XS_OFF  (A_OFF + 128 * KSE * 2)         // 169984
#define XD_OFF  (XS_OFF + 6144)
#define Q_OFF   (XD_OFF + 6144)
#define SD_OFF  (Q_OFF + 6144)
#define IDX_OFF (SD_OFF + 8192)
#define EB_OFF  (IDX_OFF + 1024)
#define GE_OFF  (EB_OFF + 512)
#define BE_OFF  (GE_OFF + 512)
#define NB_OFF  (BE_OFF + 512)
#define GN_OFF  (NB_OFF + 512)
#define BN_OFF  (GN_OFF + 512)
#define SMEM_T  (BN_OFF + 512)

// ---------------- small math ----------------
struct F3 { float x, y, z; };
__device__ __forceinline__ F3 f3sub(F3 a, F3 b) { return {a.x-b.x, a.y-b.y, a.z-b.z}; }
__device__ __forceinline__ F3 f3cross(F3 a, F3 b) {
    return {a.y*b.z - a.z*b.y, a.z*b.x - a.x*b.z, a.x*b.y - a.y*b.x};
}
__device__ __forceinline__ F3 f3nrm(F3 v) {
    float n = sqrtf(v.x*v.x + v.y*v.y + v.z*v.z);
    if (n == 0.0f) n = 1.0f;
    float i = 1.0f / n;
    return {v.x*i, v.y*i, v.z*i};
}

// ---------------- prep kernels ----------------
__global__ void wprepE_kernel(const float* __restrict__ eW) {
    int idx = blockIdx.x * 256 + threadIdx.x;
    if (idx >= 128 * KSE) return;
    int j = idx / KSE, k = idx - j * KSE;
    g_WE[idx] = __float2half_rn((k < 268) ? eW[j * 268 + k] : 0.0f);
}
__global__ void wprepN_kernel(const float* __restrict__ nW) {
    int idx = blockIdx.x * 256 + threadIdx.x;
    if (idx >= 128 * KSN) return;
    int j = idx / KSN, k = idx - j * KSN;
    g_WN[idx] = __float2half_rn((k < 96) ? nW[j * 96 + k] : 0.0f);
}
__global__ void q_kernel(const float* __restrict__ X, int N) {
    int n = blockIdx.x * blockDim.x + threadIdx.x;
    if (n >= N) return;
    float4* Qo = ((float4*)g_Q) + (size_t)n * 3;
    if (n == N - 1) {
        float4 z = make_float4(0.f, 0.f, 0.f, 0.f);
        Qo[0] = z; Qo[1] = z; Qo[2] = z;
        return;
    }
    const float* x = X + (size_t)n * 12;
    F3 X0 = {x[0], x[1], x[2]};
    F3 X1 = {x[3], x[4], x[5]};
    F3 X2 = {x[6], x[7], x[8]};
    F3 u0 = f3nrm(f3sub(X1, X0));
    F3 u1 = f3nrm(f3sub(X2, X1));
    F3 n0 = f3nrm(f3cross(u0, u1));
    F3 b1 = f3nrm(f3sub(u0, u1));
    F3 cc = f3cross(b1, n0);
    Qo[0] = make_float4(b1.x, n0.x, cc.x, 0.f);
    Qo[1] = make_float4(b1.y, n0.y, cc.y, 0.f);
    Qo[2] = make_float4(b1.z, n0.z, cc.z, 0.f);
}

// ---------------- R9-proven MMA + quad-LN + store (1x8 warp tiling) ----------------
// Warp w: rows w*16..+15 of the tile, ALL 128 output cols. No cross-warp epilogue sync.
__device__ __forceinline__ void mma_ln_store(
    uint32_t aBase, uint32_t bBase, uint32_t bRowStepBytes, int S,
    int w, int lane,
    const float* sEB, const float* sGE, const float* sBE,
    float* __restrict__ outp, int rowbase, int rowlim)
{
    float acc[64];
#pragma unroll
    for (int i = 0; i < 64; i++) acc[i] = 0.f;

#pragma unroll 1
    for (int s = 0; s < S; s++) {
        uint32_t koff = (uint32_t)(s << 5);   // 16 halves = 32 bytes
        uint32_t a0, a1, a2, a3;
        ldsm4(a0, a1, a2, a3, aBase + koff);
#pragma unroll
        for (int np = 0; np < 8; np++) {
            uint32_t b0, b1, b2, b3;
            ldsm4(b0, b1, b2, b3, bBase + koff + (uint32_t)np * bRowStepBytes);
            MMA16816(&acc[(np*2    ) * 4], a0, a1, a2, a3, b0, b2);
            MMA16816(&acc[(np*2 + 1) * 4], a0, a1, a2, a3, b1, b3);
        }
    }

    // epilogue: bias + in-quad LayerNorm + store
    int rlo = lane >> 2, q = lane & 3;
#pragma unroll
    for (int h = 0; h < 2; h++) {
        float s1 = 0.f, s2 = 0.f;
#pragma unroll
        for (int nt = 0; nt < 16; nt++) {
            int j = nt * 8 + q * 2;
            float v0 = acc[nt*4 + h*2]     + sEB[j];
            float v1 = acc[nt*4 + h*2 + 1] + sEB[j + 1];
            acc[nt*4 + h*2]     = v0;
            acc[nt*4 + h*2 + 1] = v1;
            s1 += v0 + v1;
            s2 += v0*v0 + v1*v1;
        }
        s1 += __shfl_xor_sync(0xffffffffu, s1, 1);
        s2 += __shfl_xor_sync(0xffffffffu, s2, 1);
        s1 += __shfl_xor_sync(0xffffffffu, s1, 2);
        s2 += __shfl_xor_sync(0xffffffffu, s2, 2);
        float mean = s1 * (1.f/128.f);
        float var  = (s2 - s1 * mean) * (1.f/127.f);
        float inv  = 1.f / (sqrtf(var + 1e-6f) + 1e-6f);
        int row = rowbase + (w << 4) + rlo + h * 8;
        if (row < rowlim) {
            float* op = outp + (size_t)row * 128;
#pragma unroll
            for (int nt = 0; nt < 16; nt++) {
                int j = nt * 8 + q * 2;
                float2 ov;
                ov.x = sGE[j]     * (acc[nt*4 + h*2]     - mean) * inv + sBE[j];
                ov.y = sGE[j + 1] * (acc[nt*4 + h*2 + 1] - mean) * inv + sBE[j + 1];
                *(float2*)(op + j) = ov;
            }
        }
    }
}

// ---------------- fused persistent kernel with cross-tile gather prefetch ----------------
__global__ __launch_bounds__(ETHREADS, 1) void fused_kernel(
    const float* __restrict__ X,
    const int* __restrict__ inS, const int* __restrict__ inD,
    const int* __restrict__ exS, const int* __restrict__ exD,
    const float* __restrict__ nb_, const float* __restrict__ gn, const float* __restrict__ bn,
    const float* __restrict__ eb, const float* __restrict__ ge, const float* __restrict__ be,
    float* __restrict__ out, int N, int E)
{
    extern __shared__ char sm[];
    uint32_t smb = smem_u32(sm);
    int tid = threadIdx.x;
    int w = tid >> 5, lane = tid & 31;

    __half* Ah = (__half*)(sm + A_OFF);

    // one-time: weights + params into SMEM
    for (int i = tid; i < 128 * KSE / 8; i += ETHREADS)
        ((uint4*)(sm + WE_OFF))[i] = ((const uint4*)g_WE)[i];
    for (int i = tid; i < 128 * KSN / 8; i += ETHREADS)
        ((uint4*)(sm + WN_OFF))[i] = ((const uint4*)g_WN)[i];
    if (tid < 128) {
        ((float*)(sm + EB_OFF))[tid] = eb[tid];
        ((float*)(sm + GE_OFF))[tid] = ge[tid];
        ((float*)(sm + BE_OFF))[tid] = be[tid];
        ((float*)(sm + NB_OFF))[tid] = nb_[tid];
        ((float*)(sm + GN_OFF))[tid] = gn[tid];
        ((float*)(sm + BN_OFF))[tid] = bn[tid];
        *(unsigned long long*)(Ah + tid * KSE + 268) = 0ull;   // zero-pad k=268..271 once
    }
    __syncthreads();

    float* sXs = (float*)(sm + XS_OFF);
    float* sXd = (float*)(sm + XD_OFF);
    float* sQ  = (float*)(sm + Q_OFF);
    float* sD  = (float*)(sm + SD_OFF);
    int*   sIdx = (int*)(sm + IDX_OFF);

    // ldmatrix lane address components (R9 1x8 layout)
    int lm = lane >> 3, lr = lane & 7;
    uint32_t rowsel = (uint32_t)(((lm & 1) << 3) + lr);
    uint32_t colByte = (uint32_t)((lm >> 1) << 4);
    uint32_t aBase  = smb + A_OFF  + ((uint32_t)(w << 4) + rowsel) * (KSE * 2u) + colByte;
    uint32_t bBaseE = smb + WE_OFF + rowsel * (KSE * 2u) + colByte;
    uint32_t bBaseN = smb + WN_OFF + rowsel * (KSN * 2u) + colByte;

    float* outIn = out + (size_t)N * 128;
    float* outEx = outIn + (size_t)E * 128;

    int g = gridDim.x;
    int ntE = (E + 127) >> 7;
    int ntN = (N + 127) >> 7;
    int ntot = 2 * ntE + ntN;

    const float4* X4 = (const float4*)X;
    const float4* Q4 = (const float4*)g_Q;

    // prefetch state
    float4 pXs[2], pXd[2], pQ[2];
    int pIdx = 0;
    pXs[0] = pXs[1] = pXd[0] = pXd[1] = pQ[0] = pQ[1] = make_float4(0.f, 0.f, 0.f, 0.f);

    // ---------------- prologue: fill state for first tile ----------------
    int t0 = blockIdx.x;
    {
        // idx(t0) -> sIdx (t0 < gridDim <= ntE, always an edge tile, but keep general)
        if (t0 < 2 * ntE) {
            int set = (t0 >= ntE);
            int tl = set ? (t0 - ntE) : t0;
            const int* sp = set ? exS : inS;
            const int* dp = set ? exD : inD;
            int e = (tl << 7) + (tid & 127);
            if (e >= E) e = E - 1;
            pIdx = (tid < 128) ? sp[e] : dp[e];
        }
        sIdx[tid] = pIdx;
        __syncthreads();
        // gather(t0) -> regs
        if (t0 < 2 * ntE) {
#pragma unroll
            for (int s2 = 0; s2 < 2; s2++) {
                int i = tid + (s2 << 8);
                if (i < 384) {
                    int e = i / 3, r = i - e * 3;
                    pXs[s2] = X4[(size_t)sIdx[e] * 3 + r];
                    pXd[s2] = X4[(size_t)sIdx[128 + e] * 3 + r];
                    pQ[s2]  = Q4[(size_t)sIdx[e] * 3 + r];
                }
            }
        } else {
            int b2 = (t0 - 2 * ntE) << 7;
#pragma unroll
            for (int s2 = 0; s2 < 2; s2++) {
                int i = tid + (s2 << 8);
                if (i < 384) {
                    int e = i / 3, r = i - e * 3;
                    int n = b2 + e; if (n >= N) n = N - 1;
                    pXs[s2] = X4[(size_t)n * 3 + r];
                }
            }
        }
        // idx(t0+g) -> pIdx
        int tpp = t0 + g; if (tpp >= ntot) tpp = ntot - 1;
        if (tpp < 2 * ntE) {
            int set = (tpp >= ntE);
            int tl = set ? (tpp - ntE) : tpp;
            const int* sp = set ? exS : inS;
            const int* dp = set ? exD : inD;
            int e = (tl << 7) + (tid & 127);
            if (e >= E) e = E - 1;
            pIdx = (tid < 128) ? sp[e] : dp[e];
        }
        __syncthreads();   // order prologue sIdx reads vs first commit's sIdx write
    }

    // ---------------- main loop ----------------
    for (int tcur = t0; tcur < ntot; tcur += g) {
        bool isE = (tcur < 2 * ntE);
        int base;
        float* outp;
        if (isE) {
            int set = (tcur >= ntE);
            int tl = set ? (tcur - ntE) : tcur;
            base = tl << 7;
            outp = set ? outEx : outIn;
        } else {
            base = (tcur - 2 * ntE) << 7;
            outp = out;
        }

        // ---- commit prefetched state (tile tcur gathers + idx(tcur+g)) ----
#pragma unroll
        for (int s2 = 0; s2 < 2; s2++) {
            int i = tid + (s2 << 8);
            if (i < 384) {
                ((float4*)sXs)[i] = pXs[s2];
                if (isE) {
                    ((float4*)sXd)[i] = pXd[s2];
                    ((float4*)sQ )[i] = pQ[s2];
                }
            }
        }
        sIdx[tid] = pIdx;
        __syncthreads();

        // ---- prefetch: gather(tcur+g) via sIdx, idx(tcur+2g) ----
        {
            int tn = tcur + g; if (tn >= ntot) tn = ntot - 1;
            if (tn < 2 * ntE) {
#pragma unroll
                for (int s2 = 0; s2 < 2; s2++) {
                    int i = tid + (s2 << 8);
                    if (i < 384) {
                        int e = i / 3, r = i - e * 3;
                        pXs[s2] = X4[(size_t)sIdx[e] * 3 + r];
                        pXd[s2] = X4[(size_t)sIdx[128 + e] * 3 + r];
                        pQ[s2]  = Q4[(size_t)sIdx[e] * 3 + r];
                    }
                }
            } else {
                int b2 = (tn - 2 * ntE) << 7;
#pragma unroll
                for (int s2 = 0; s2 < 2; s2++) {
                    int i = tid + (s2 << 8);
                    if (i < 384) {
                        int e = i / 3, r = i - e * 3;
                        int n = b2 + e; if (n >= N) n = N - 1;
                        pXs[s2] = X4[(size_t)n * 3 + r];
                    }
                }
            }
            int tpp = tcur + 2 * g; if (tpp >= ntot) tpp = ntot - 1;
            if (tpp < 2 * ntE) {
                int set2 = (tpp >= ntE);
                int tl2 = set2 ? (tpp - ntE) : tpp;
                const int* sp = set2 ? exS : inS;
                const int* dp = set2 ? exD : inD;
                int e = (tl2 << 7) + (tid & 127);
                if (e >= E) e = E - 1;
                pIdx = (tid < 128) ? sp[e] : dp[e];
            }
        }

        // ---- features ----
        if (isE) {
            // distances: 16 pairs x 128 edges
            for (int i = tid; i < 2048; i += ETHREADS) {
                int p = i >> 7, e = i & 127;
                int a = c_EPA[p], b = c_EPB[p];
                const float* xs = sXs + e*12 + a*3;
                const float* xd = sXd + e*12 + b*3;
                float dx = xs[0]-xd[0], dy = xs[1]-xd[1], dz = xs[2]-xd[2];
                sD[(p << 7) + e] = sqrtf(dx*dx + dy*dy + dz*dz + 1e-6f);
            }
            // direct features k=256..267
            {
                int e = tid & 127, hf = tid >> 7;
                const float* xs = sXs + e*12;
                const float* xd = sXd + e*12;
                const float* q  = sQ  + e*12;
#pragma unroll
                for (int ii = 0; ii < 2; ii++) {
                    int a = hf * 2 + ii;
                    int da = c_DSEL[a];
                    float v0 = xd[da*3+0] - xs[0];
                    float v1 = xd[da*3+1] - xs[1];
                    float v2 = xd[da*3+2] - xs[2];
                    float d0 = q[0]*v0 + q[1]*v1 + q[2]*v2;
                    float d1 = q[4]*v0 + q[5]*v1 + q[6]*v2;
                    float d2 = q[8]*v0 + q[9]*v1 + q[10]*v2;
                    float nn = sqrtf(d0*d0 + d1*d1 + d2*d2);
                    if (nn == 0.0f) nn = 1.0f;
                    float inv = 1.0f / nn;
                    int k = 256 + a * 3;
                    Ah[e * KSE + k]     = __float2half_rn(d0 * inv);
                    Ah[e * KSE + k + 1] = __float2half_rn(d1 * inv);
                    Ah[e * KSE + k + 2] = __float2half_rn(d2 * inv);
                }
            }
            __syncthreads();

            // RBF: thread (e, hf) does 8 mus for each of 16 pairs
            {
                int e = tid & 127, hf = tid >> 7;
                int r0 = hf * 8;
#pragma unroll 1
                for (int p = 0; p < 16; p++) {
                    float d = sD[(p << 7) + e];
                    uint32_t pk[4];
#pragma unroll
                    for (int j2 = 0; j2 < 4; j2++) {
                        float u0 = (d - (float)(r0 + 2*j2)     * (20.0f/15.0f)) * 0.8f;
                        float u1 = (d - (float)(r0 + 2*j2 + 1) * (20.0f/15.0f)) * 0.8f;
                        __half2 h = __floats2half2_rn(__expf(-u0*u0), __expf(-u1*u1));
                        pk[j2] = *(uint32_t*)&h;
                    }
                    *(uint4*)(Ah + e * KSE + p * 16 + r0) = make_uint4(pk[0], pk[1], pk[2], pk[3]);
                }
            }
            __syncthreads();

            mma_ln_store(aBase, bBaseE, (uint32_t)(16 * KSE * 2), 17, w, lane,
                         (const float*)(sm + EB_OFF), (const float*)(sm + GE_OFF), (const float*)(sm + BE_OFF),
                         outp, base, E);
        } else {
            // 6 intra-node distances
            for (int i = tid; i < 768; i += ETHREADS) {
                int p = i >> 7, e = i & 127;
                int a = c_NPA[p], b = c_NPB[p];
                const float* xa = sXs + e*12 + a*3;
                const float* xb = sXs + e*12 + b*3;
                float dx = xa[0]-xb[0], dy = xa[1]-xb[1], dz = xa[2]-xb[2];
                sD[(p << 7) + e] = sqrtf(dx*dx + dy*dy + dz*dz + 1e-6f);
            }
            __syncthreads();

            // RBF: 96 features (6 pairs x 16 mus) into A (KSE stride, cols 0..95)
            {
                int e = tid & 127, hf = tid >> 7;
                int r0 = hf * 8;
#pragma unroll 1
                for (int p = 0; p < 6; p++) {
                    float d = sD[(p << 7) + e];
                    uint32_t pk[4];
#pragma unroll
                    for (int j2 = 0; j2 < 4; j2++) {
                        float u0 = (d - (float)(r0 + 2*j2)     * (20.0f/15.0f)) * 0.8f;
                        float u1 = (d - (float)(r0 + 2*j2 + 1) * (20.0f/15.0f)) * 0.8f;
                        __half2 h = __floats2half2_rn(__expf(-u0*u0), __expf(-u1*u1));
                        pk[j2] = *(uint32_t*)&h;
                    }
                    *(uint4*)(Ah + e * KSE + p * 16 + r0) = make_uint4(pk[0], pk[1], pk[2], pk[3]);
                }
            }
            __syncthreads();

            mma_ln_store(aBase, bBaseN, (uint32_t)(16 * KSN * 2), 6, w, lane,
                         (const float*)(sm + NB_OFF), (const float*)(sm + GN_OFF), (const float*)(sm + BN_OFF),
                         out, base, N);
        }
        // next iteration's commit is ordered against this tile's ldsm reads by
        // the next iteration's post-commit __syncthreads (commit writes happen
        // after every thread finished its MMA; barrier publishes them before features)
    }
}

// ---------------- launch ----------------
extern "C" void kernel_launch(void* const* d_in, const int* in_sizes, int n_in,
                              void* d_out, int out_size)
{
    const float* X   = (const float*)d_in[0];
    const int*   Ein = (const int*)  d_in[1];
    const int*   Eex = (const int*)  d_in[2];
    const float* nW  = (const float*)d_in[3];
    const float* nb  = (const float*)d_in[4];
    const float* eW  = (const float*)d_in[5];
    const float* eb  = (const float*)d_in[6];
    const float* gn  = (const float*)d_in[7];
    const float* bn  = (const float*)d_in[8];
    const float* ge  = (const float*)d_in[9];
    const float* be  = (const float*)d_in[10];

    int N = in_sizes[0] / 12;
    int E = in_sizes[1] / 2;
    float* out = (float*)d_out;

    cudaFuncSetAttribute(fused_kernel, cudaFuncAttributeMaxDynamicSharedMemorySize, SMEM_T);

    wprepE_kernel<<<(128*KSE + 255)/256, 256>>>(eW);
    wprepN_kernel<<<(128*KSN + 255)/256, 256>>>(nW);
    q_kernel<<<(N + 255)/256, 256>>>(X, N);

    fused_kernel<<<EGRID, ETHREADS, SMEM_T>>>(
        X, Ein, Ein + E, Eex, Eex + E,
        nb, gn, bn, eb, ge, be, out, N, E);
}

// round 13
// speedup vs baseline: 2.1489x; 1.1960x over previous
#include <cuda_runtime.h>
#include <cuda_fp16.h>
#include <cstdint>

// ---------------- constants ----------------
#define NMAX 50048
#define ETHREADS 256
#define EGRID 152
#define KSE 280     // edge A/W k-stride in halves (560B rows: ldmatrix conflict-free)
#define KSN 104     // node W k-stride in halves (208B rows: conflict-free)

// RBF recurrence constants: sigma=1.25, delta=20/15
#define RBF_INVS2 0.64f          // 1/sigma^2
#define RBF_K1    1.70666667f    // 2*delta/sigma^2
#define RBF_K2   -1.13777778f    // -delta^2/sigma^2
#define RBF_G     0.10273983f    // exp(-2*delta^2/sigma^2)

// ---------------- device scratch ----------------
__device__ __align__(16) float g_Q[NMAX * 12];
__device__ __align__(16) __half g_WE[128 * KSE];   // fp16 edge_W [j][k]
__device__ __align__(16) __half g_WN[128 * KSN];   // fp16 node_W [j][k]

__constant__ int c_EPA[16] = {1,1,2,1,0,1,3,2,2,0,2,3,0,0,3,3};
__constant__ int c_EPB[16] = {1,2,1,0,1,3,1,2,0,2,3,2,0,3,0,3};
__constant__ int c_NPA[6]  = {1,1,1,0,0,3};
__constant__ int c_NPB[6]  = {0,2,3,2,3,2};
__constant__ int c_DSEL[4] = {1,0,2,3};

// ---------------- PTX helpers (baseline ISA only) ----------------
__device__ __forceinline__ uint32_t smem_u32(const void* p) {
    uint32_t a;
    asm("{ .reg .u64 t; cvta.to.shared.u64 t, %1; cvt.u32.u64 %0, t; }" : "=r"(a) : "l"(p));
    return a;
}
__device__ __forceinline__ void ldsm4(uint32_t& r0, uint32_t& r1, uint32_t& r2, uint32_t& r3, uint32_t a) {
    asm volatile("ldmatrix.sync.aligned.m8n8.x4.shared.b16 {%0,%1,%2,%3}, [%4];"
        : "=r"(r0), "=r"(r1), "=r"(r2), "=r"(r3) : "r"(a));
}
#define MMA16816(c, a0,a1,a2,a3, b0,b1) \
    asm volatile("mma.sync.aligned.m16n8k16.row.col.f32.f16.f16.f32 " \
        "{%0,%1,%2,%3}, {%4,%5,%6,%7}, {%8,%9}, {%0,%1,%2,%3};" \
        : "+f"((c)[0]), "+f"((c)[1]), "+f"((c)[2]), "+f"((c)[3]) \
        : "r"(a0), "r"(a1), "r"(a2), "r"(a3), "r"(b0), "r"(b1))

// ---------------- SMEM layout (bytes) ----------------
#define WE_OFF  0
#define WN_OFF  (WE_OFF + 128 * KSE * 2)        // 71680
#define A_OFF   (WN_OFF + 128 * KSN * 2)        // 98304
#define XS_OFF  (A_OFF + 128 * KSE * 2)         // 169984
#define XD_OFF  (XS_OFF + 6144)
#define Q_OFF   (XD_OFF + 6144)
#define IDX_OFF (Q_OFF + 6144)
#define EB_OFF  (IDX_OFF + 1024)
#define GE_OFF  (EB_OFF + 512)
#define BE_OFF  (GE_OFF + 512)
#define NB_OFF  (BE_OFF + 512)
#define GN_OFF  (NB_OFF + 512)
#define BN_OFF  (GN_OFF + 512)
#define SMEM_T  (BN_OFF + 512)

// ---------------- small math ----------------
struct F3 { float x, y, z; };
__device__ __forceinline__ F3 f3sub(F3 a, F3 b) { return {a.x-b.x, a.y-b.y, a.z-b.z}; }
__device__ __forceinline__ F3 f3cross(F3 a, F3 b) {
    return {a.y*b.z - a.z*b.y, a.z*b.x - a.x*b.z, a.x*b.y - a.y*b.x};
}
__device__ __forceinline__ F3 f3nrm(F3 v) {
    float n = sqrtf(v.x*v.x + v.y*v.y + v.z*v.z);
    if (n == 0.0f) n = 1.0f;
    float i = 1.0f / n;
    return {v.x*i, v.y*i, v.z*i};
}

// 16-mu RBF row via recurrence; writes 32B (16 halves) at col0 = p*16
__device__ __forceinline__ void rbf_row16(__half* dst, float t /*= d^2+eps*/) {
    float d = sqrtf(t);
    float f = __expf(-t * RBF_INVS2);      // f_0
    float r = __expf(d * RBF_K1 + RBF_K2); // ratio_0
    uint32_t pk[8];
#pragma unroll
    for (int m = 0; m < 8; m++) {
        float f0 = f; f *= r; r *= RBF_G;
        float f1 = f; f *= r; r *= RBF_G;
        __half2 h = __floats2half2_rn(f0, f1);
        pk[m] = *(uint32_t*)&h;
    }
    *(uint4*)(dst)     = make_uint4(pk[0], pk[1], pk[2], pk[3]);
    *(uint4*)(dst + 8) = make_uint4(pk[4], pk[5], pk[6], pk[7]);
}

// ---------------- prep kernels ----------------
__global__ void wprepE_kernel(const float* __restrict__ eW) {
    int idx = blockIdx.x * 256 + threadIdx.x;
    if (idx >= 128 * KSE) return;
    int j = idx / KSE, k = idx - j * KSE;
    g_WE[idx] = __float2half_rn((k < 268) ? eW[j * 268 + k] : 0.0f);
}
__global__ void wprepN_kernel(const float* __restrict__ nW) {
    int idx = blockIdx.x * 256 + threadIdx.x;
    if (idx >= 128 * KSN) return;
    int j = idx / KSN, k = idx - j * KSN;
    g_WN[idx] = __float2half_rn((k < 96) ? nW[j * 96 + k] : 0.0f);
}
__global__ void q_kernel(const float* __restrict__ X, int N) {
    int n = blockIdx.x * blockDim.x + threadIdx.x;
    if (n >= N) return;
    float4* Qo = ((float4*)g_Q) + (size_t)n * 3;
    if (n == N - 1) {
        float4 z = make_float4(0.f, 0.f, 0.f, 0.f);
        Qo[0] = z; Qo[1] = z; Qo[2] = z;
        return;
    }
    const float* x = X + (size_t)n * 12;
    F3 X0 = {x[0], x[1], x[2]};
    F3 X1 = {x[3], x[4], x[5]};
    F3 X2 = {x[6], x[7], x[8]};
    F3 u0 = f3nrm(f3sub(X1, X0));
    F3 u1 = f3nrm(f3sub(X2, X1));
    F3 n0 = f3nrm(f3cross(u0, u1));
    F3 b1 = f3nrm(f3sub(u0, u1));
    F3 cc = f3cross(b1, n0);
    Qo[0] = make_float4(b1.x, n0.x, cc.x, 0.f);
    Qo[1] = make_float4(b1.y, n0.y, cc.y, 0.f);
    Qo[2] = make_float4(b1.z, n0.z, cc.z, 0.f);
}

// ---------------- MMA + quad-LN + store (R9-proven 1x8 warp tiling) ----------------
__device__ __forceinline__ void mma_ln_store(
    uint32_t aBase, uint32_t bBase, uint32_t bRowStepBytes, int S,
    int w, int lane,
    const float* sEB, const float* sGE, const float* sBE,
    float* __restrict__ outp, int rowbase, int rowlim)
{
    float acc[64];
#pragma unroll
    for (int i = 0; i < 64; i++) acc[i] = 0.f;

#pragma unroll 2
    for (int s = 0; s < S; s++) {
        uint32_t koff = (uint32_t)(s << 5);   // 16 halves = 32 bytes
        uint32_t a0, a1, a2, a3;
        ldsm4(a0, a1, a2, a3, aBase + koff);
#pragma unroll
        for (int np = 0; np < 8; np++) {
            uint32_t b0, b1, b2, b3;
            ldsm4(b0, b1, b2, b3, bBase + koff + (uint32_t)np * bRowStepBytes);
            MMA16816(&acc[(np*2    ) * 4], a0, a1, a2, a3, b0, b2);
            MMA16816(&acc[(np*2 + 1) * 4], a0, a1, a2, a3, b1, b3);
        }
    }

    // epilogue: bias + in-quad LayerNorm + store
    int rlo = lane >> 2, q = lane & 3;
#pragma unroll
    for (int h = 0; h < 2; h++) {
        float s1 = 0.f, s2 = 0.f;
#pragma unroll
        for (int nt = 0; nt < 16; nt++) {
            int j = nt * 8 + q * 2;
            float v0 = acc[nt*4 + h*2]     + sEB[j];
            float v1 = acc[nt*4 + h*2 + 1] + sEB[j + 1];
            acc[nt*4 + h*2]     = v0;
            acc[nt*4 + h*2 + 1] = v1;
            s1 += v0 + v1;
            s2 += v0*v0 + v1*v1;
        }
        s1 += __shfl_xor_sync(0xffffffffu, s1, 1);
        s2 += __shfl_xor_sync(0xffffffffu, s2, 1);
        s1 += __shfl_xor_sync(0xffffffffu, s1, 2);
        s2 += __shfl_xor_sync(0xffffffffu, s2, 2);
        float mean = s1 * (1.f/128.f);
        float var  = (s2 - s1 * mean) * (1.f/127.f);
        float inv  = 1.f / (sqrtf(var + 1e-6f) + 1e-6f);
        int row = rowbase + (w << 4) + rlo + h * 8;
        if (row < rowlim) {
            float* op = outp + (size_t)row * 128;
#pragma unroll
            for (int nt = 0; nt < 16; nt++) {
                int j = nt * 8 + q * 2;
                float2 ov;
                ov.x = sGE[j]     * (acc[nt*4 + h*2]     - mean) * inv + sBE[j];
                ov.y = sGE[j + 1] * (acc[nt*4 + h*2 + 1] - mean) * inv + sBE[j + 1];
                *(float2*)(op + j) = ov;
            }
        }
    }
}

// ---------------- fused persistent kernel with cross-tile gather prefetch ----------------
__global__ __launch_bounds__(ETHREADS, 1) void fused_kernel(
    const float* __restrict__ X,
    const int* __restrict__ inS, const int* __restrict__ inD,
    const int* __restrict__ exS, const int* __restrict__ exD,
    const float* __restrict__ nb_, const float* __restrict__ gn, const float* __restrict__ bn,
    const float* __restrict__ eb, const float* __restrict__ ge, const float* __restrict__ be,
    float* __restrict__ out, int N, int E)
{
    extern __shared__ char sm[];
    uint32_t smb = smem_u32(sm);
    int tid = threadIdx.x;
    int w = tid >> 5, lane = tid & 31;

    __half* Ah = (__half*)(sm + A_OFF);

    // one-time: weights + params into SMEM
    for (int i = tid; i < 128 * KSE / 8; i += ETHREADS)
        ((uint4*)(sm + WE_OFF))[i] = ((const uint4*)g_WE)[i];
    for (int i = tid; i < 128 * KSN / 8; i += ETHREADS)
        ((uint4*)(sm + WN_OFF))[i] = ((const uint4*)g_WN)[i];
    if (tid < 128) {
        ((float*)(sm + EB_OFF))[tid] = eb[tid];
        ((float*)(sm + GE_OFF))[tid] = ge[tid];
        ((float*)(sm + BE_OFF))[tid] = be[tid];
        ((float*)(sm + NB_OFF))[tid] = nb_[tid];
        ((float*)(sm + GN_OFF))[tid] = gn[tid];
        ((float*)(sm + BN_OFF))[tid] = bn[tid];
        *(unsigned long long*)(Ah + tid * KSE + 268) = 0ull;   // zero-pad k=268..271 once
    }
    __syncthreads();

    float* sXs = (float*)(sm + XS_OFF);
    float* sXd = (float*)(sm + XD_OFF);
    float* sQ  = (float*)(sm + Q_OFF);
    int*   sIdx = (int*)(sm + IDX_OFF);

    // ldmatrix lane address components (1x8 layout)
    int lm = lane >> 3, lr = lane & 7;
    uint32_t rowsel = (uint32_t)(((lm & 1) << 3) + lr);
    uint32_t colByte = (uint32_t)((lm >> 1) << 4);
    uint32_t aBase  = smb + A_OFF  + ((uint32_t)(w << 4) + rowsel) * (KSE * 2u) + colByte;
    uint32_t bBaseE = smb + WE_OFF + rowsel * (KSE * 2u) + colByte;
    uint32_t bBaseN = smb + WN_OFF + rowsel * (KSN * 2u) + colByte;

    float* outIn = out + (size_t)N * 128;
    float* outEx = outIn + (size_t)E * 128;

    int g = gridDim.x;
    int ntE = (E + 127) >> 7;
    int ntN = (N + 127) >> 7;
    int ntot = 2 * ntE + ntN;

    const float4* X4 = (const float4*)X;
    const float4* Q4 = (const float4*)g_Q;

    // prefetch state
    float4 pXs[2], pXd[2], pQ[2];
    int pIdx = 0;
    pXs[0] = pXs[1] = pXd[0] = pXd[1] = pQ[0] = pQ[1] = make_float4(0.f, 0.f, 0.f, 0.f);

    // ---------------- prologue: fill state for first tile ----------------
    int t0 = blockIdx.x;
    {
        if (t0 < 2 * ntE) {
            int set = (t0 >= ntE);
            int tl = set ? (t0 - ntE) : t0;
            const int* sp = set ? exS : inS;
            const int* dp = set ? exD : inD;
            int e = (tl << 7) + (tid & 127);
            if (e >= E) e = E - 1;
            pIdx = (tid < 128) ? sp[e] : dp[e];
        }
        sIdx[tid] = pIdx;
        __syncthreads();
        if (t0 < 2 * ntE) {
#pragma unroll
            for (int s2 = 0; s2 < 2; s2++) {
                int i = tid + (s2 << 8);
                if (i < 384) {
                    int e = i / 3, r = i - e * 3;
                    pXs[s2] = X4[(size_t)sIdx[e] * 3 + r];
                    pXd[s2] = X4[(size_t)sIdx[128 + e] * 3 + r];
                    pQ[s2]  = Q4[(size_t)sIdx[e] * 3 + r];
                }
            }
        } else {
            int b2 = (t0 - 2 * ntE) << 7;
#pragma unroll
            for (int s2 = 0; s2 < 2; s2++) {
                int i = tid + (s2 << 8);
                if (i < 384) {
                    int e = i / 3, r = i - e * 3;
                    int n = b2 + e; if (n >= N) n = N - 1;
                    pXs[s2] = X4[(size_t)n * 3 + r];
                }
            }
        }
        int tpp = t0 + g; if (tpp >= ntot) tpp = ntot - 1;
        if (tpp < 2 * ntE) {
            int set = (tpp >= ntE);
            int tl = set ? (tpp - ntE) : tpp;
            const int* sp = set ? exS : inS;
            const int* dp = set ? exD : inD;
            int e = (tl << 7) + (tid & 127);
            if (e >= E) e = E - 1;
            pIdx = (tid < 128) ? sp[e] : dp[e];
        }
        __syncthreads();
    }

    // ---------------- main loop ----------------
    for (int tcur = t0; tcur < ntot; tcur += g) {
        bool isE = (tcur < 2 * ntE);
        int base;
        float* outp;
        if (isE) {
            int set = (tcur >= ntE);
            int tl = set ? (tcur - ntE) : tcur;
            base = tl << 7;
            outp = set ? outEx : outIn;
        } else {
            base = (tcur - 2 * ntE) << 7;
            outp = out;
        }

        // ---- commit prefetched state (tile tcur gathers + idx(tcur+g)) ----
#pragma unroll
        for (int s2 = 0; s2 < 2; s2++) {
            int i = tid + (s2 << 8);
            if (i < 384) {
                ((float4*)sXs)[i] = pXs[s2];
                if (isE) {
                    ((float4*)sXd)[i] = pXd[s2];
                    ((float4*)sQ )[i] = pQ[s2];
                }
            }
        }
        sIdx[tid] = pIdx;
        __syncthreads();

        // ---- prefetch: gather(tcur+g) via sIdx, idx(tcur+2g) ----
        {
            int tn = tcur + g; if (tn >= ntot) tn = ntot - 1;
            if (tn < 2 * ntE) {
#pragma unroll
                for (int s2 = 0; s2 < 2; s2++) {
                    int i = tid + (s2 << 8);
                    if (i < 384) {
                        int e = i / 3, r = i - e * 3;
                        pXs[s2] = X4[(size_t)sIdx[e] * 3 + r];
                        pXd[s2] = X4[(size_t)sIdx[128 + e] * 3 + r];
                        pQ[s2]  = Q4[(size_t)sIdx[e] * 3 + r];
                    }
                }
            } else {
                int b2 = (tn - 2 * ntE) << 7;
#pragma unroll
                for (int s2 = 0; s2 < 2; s2++) {
                    int i = tid + (s2 << 8);
                    if (i < 384) {
                        int e = i / 3, r = i - e * 3;
                        int n = b2 + e; if (n >= N) n = N - 1;
                        pXs[s2] = X4[(size_t)n * 3 + r];
                    }
                }
            }
            int tpp = tcur + 2 * g; if (tpp >= ntot) tpp = ntot - 1;
            if (tpp < 2 * ntE) {
                int set2 = (tpp >= ntE);
                int tl2 = set2 ? (tpp - ntE) : tpp;
                const int* sp = set2 ? exS : inS;
                const int* dp = set2 ? exD : inD;
                int e = (tl2 << 7) + (tid & 127);
                if (e >= E) e = E - 1;
                pIdx = (tid < 128) ? sp[e] : dp[e];
            }
        }

        // ---- features (single phase; RBF computes its own distances) ----
        if (isE) {
            int e = tid & 127, hf = tid >> 7;
            const float* xs = sXs + e*12;
            const float* xd = sXd + e*12;
            // direct features k=256..267 (2 directions per thread)
            {
                const float* q = sQ + e*12;
#pragma unroll
                for (int ii = 0; ii < 2; ii++) {
                    int a = hf * 2 + ii;
                    int da = c_DSEL[a];
                    float v0 = xd[da*3+0] - xs[0];
                    float v1 = xd[da*3+1] - xs[1];
                    float v2 = xd[da*3+2] - xs[2];
                    float d0 = q[0]*v0 + q[1]*v1 + q[2]*v2;
                    float d1 = q[4]*v0 + q[5]*v1 + q[6]*v2;
                    float d2 = q[8]*v0 + q[9]*v1 + q[10]*v2;
                    float nn = sqrtf(d0*d0 + d1*d1 + d2*d2);
                    if (nn == 0.0f) nn = 1.0f;
                    float inv = 1.0f / nn;
                    int k = 256 + a * 3;
                    Ah[e * KSE + k]     = __float2half_rn(d0 * inv);
                    Ah[e * KSE + k + 1] = __float2half_rn(d1 * inv);
                    Ah[e * KSE + k + 2] = __float2half_rn(d2 * inv);
                }
            }
            // RBF: thread handles pairs hf*8..+7, full 16-mu row each (recurrence)
#pragma unroll 1
            for (int i = 0; i < 8; i++) {
                int p = (hf << 3) + i;
                int a = c_EPA[p], b = c_EPB[p];
                float dx = xs[a*3+0] - xd[b*3+0];
                float dy = xs[a*3+1] - xd[b*3+1];
                float dz = xs[a*3+2] - xd[b*3+2];
                float t = dx*dx + dy*dy + dz*dz + 1e-6f;
                rbf_row16(Ah + e * KSE + (p << 4), t);
            }
            __syncthreads();

            mma_ln_store(aBase, bBaseE, (uint32_t)(16 * KSE * 2), 17, w, lane,
                         (const float*)(sm + EB_OFF), (const float*)(sm + GE_OFF), (const float*)(sm + BE_OFF),
                         outp, base, E);
        } else {
            int e = tid & 127, hf = tid >> 7;
            const float* xs = sXs + e*12;
            // RBF: 6 pairs split 3/3 across hf (recurrence, distances inline)
#pragma unroll 1
            for (int i = 0; i < 3; i++) {
                int p = hf * 3 + i;
                int a = c_NPA[p], b = c_NPB[p];
                float dx = xs[a*3+0] - xs[b*3+0];
                float dy = xs[a*3+1] - xs[b*3+1];
                float dz = xs[a*3+2] - xs[b*3+2];
                float t = dx*dx + dy*dy + dz*dz + 1e-6f;
                rbf_row16(Ah + e * KSE + (p << 4), t);
            }
            __syncthreads();

            mma_ln_store(aBase, bBaseN, (uint32_t)(16 * KSN * 2), 6, w, lane,
                         (const float*)(sm + NB_OFF), (const float*)(sm + GN_OFF), (const float*)(sm + BN_OFF),
                         out, base, N);
        }
    }
}

// ---------------- launch ----------------
extern "C" void kernel_launch(void* const* d_in, const int* in_sizes, int n_in,
                              void* d_out, int out_size)
{
    const float* X   = (const float*)d_in[0];
    const int*   Ein = (const int*)  d_in[1];
    const int*   Eex = (const int*)  d_in[2];
    const float* nW  = (const float*)d_in[3];
    const float* nb  = (const float*)d_in[4];
    const float* eW  = (const float*)d_in[5];
    const float* eb  = (const float*)d_in[6];
    const float* gn  = (const float*)d_in[7];
    const float* bn  = (const float*)d_in[8];
    const float* ge  = (const float*)d_in[9];
    const float* be  = (const float*)d_in[10];

    int N = in_sizes[0] / 12;
    int E = in_sizes[1] / 2;
    float* out = (float*)d_out;

    cudaFuncSetAttribute(fused_kernel, cudaFuncAttributeMaxDynamicSharedMemorySize, SMEM_T);

    wprepE_kernel<<<(128*KSE + 255)/256, 256>>>(eW);
    wprepN_kernel<<<(128*KSN + 255)/256, 256>>>(nW);
    q_kernel<<<(N + 255)/256, 256>>>(X, N);

    fused_kernel<<<EGRID, ETHREADS, SMEM_T>>>(
        X, Ein, Ein + E, Eex, Eex + E,
        nb, gn, bn, eb, ge, be, out, N, E);
}

// round 14
// speedup vs baseline: 2.3579x; 1.0973x over previous
#include <cuda_runtime.h>
#include <cuda_fp16.h>
#include <cstdint>

// ---------------- constants ----------------
#define NMAX 50048
#define ETHREADS 256
#define EGRID 152
#define KSE 280     // edge A/W k-stride in halves (560B rows: ldmatrix conflict-free)
#define KSN 104     // node W k-stride in halves (208B rows: conflict-free)

// RBF recurrence constants: sigma=1.25, delta=20/15
#define RBF_INVS2 0.64f          // 1/sigma^2
#define RBF_K1    1.70666667f    // 2*delta/sigma^2
#define RBF_K2   -1.13777778f    // -delta^2/sigma^2
#define RBF_G     0.10273983f    // exp(-2*delta^2/sigma^2)

// ---------------- device scratch ----------------
__device__ __align__(16) float g_Q[NMAX * 12];
__device__ __align__(16) __half g_WE[128 * KSE];   // fp16 edge_W [j][k]
__device__ __align__(16) __half g_WN[128 * KSN];   // fp16 node_W [j][k]

__constant__ int c_NPA[6]  = {1,1,1,0,0,3};
__constant__ int c_NPB[6]  = {0,2,3,2,3,2};

// ---------------- PTX helpers (baseline ISA only) ----------------
__device__ __forceinline__ uint32_t smem_u32(const void* p) {
    uint32_t a;
    asm("{ .reg .u64 t; cvta.to.shared.u64 t, %1; cvt.u32.u64 %0, t; }" : "=r"(a) : "l"(p));
    return a;
}
__device__ __forceinline__ void ldsm4(uint32_t& r0, uint32_t& r1, uint32_t& r2, uint32_t& r3, uint32_t a) {
    asm volatile("ldmatrix.sync.aligned.m8n8.x4.shared.b16 {%0,%1,%2,%3}, [%4];"
        : "=r"(r0), "=r"(r1), "=r"(r2), "=r"(r3) : "r"(a));
}
#define MMA16816(c, a0,a1,a2,a3, b0,b1) \
    asm volatile("mma.sync.aligned.m16n8k16.row.col.f32.f16.f16.f32 " \
        "{%0,%1,%2,%3}, {%4,%5,%6,%7}, {%8,%9}, {%0,%1,%2,%3};" \
        : "+f"((c)[0]), "+f"((c)[1]), "+f"((c)[2]), "+f"((c)[3]) \
        : "r"(a0), "r"(a1), "r"(a2), "r"(a3), "r"(b0), "r"(b1))

// ---------------- SMEM layout (bytes) ----------------
#define WE_OFF  0
#define WN_OFF  (WE_OFF + 128 * KSE * 2)        // 71680
#define A_OFF   (WN_OFF + 128 * KSN * 2)        // 98304
#define XS_OFF  (A_OFF + 128 * KSE * 2)         // 169984
#define XD_OFF  (XS_OFF + 6144)
#define Q_OFF   (XD_OFF + 6144)
#define IDX_OFF (Q_OFF + 6144)
#define EB_OFF  (IDX_OFF + 1024)
#define GE_OFF  (EB_OFF + 512)
#define BE_OFF  (GE_OFF + 512)
#define NB_OFF  (BE_OFF + 512)
#define GN_OFF  (NB_OFF + 512)
#define BN_OFF  (GN_OFF + 512)
#define SMEM_T  (BN_OFF + 512)

// ---------------- small math ----------------
struct F3 { float x, y, z; };
__device__ __forceinline__ F3 f3sub(F3 a, F3 b) { return {a.x-b.x, a.y-b.y, a.z-b.z}; }
__device__ __forceinline__ F3 f3cross(F3 a, F3 b) {
    return {a.y*b.z - a.z*b.y, a.z*b.x - a.x*b.z, a.x*b.y - a.y*b.x};
}
__device__ __forceinline__ F3 f3nrm(F3 v) {
    float n = sqrtf(v.x*v.x + v.y*v.y + v.z*v.z);
    if (n == 0.0f) n = 1.0f;
    float i = 1.0f / n;
    return {v.x*i, v.y*i, v.z*i};
}

// 16-mu RBF row via recurrence; writes 32B (16 halves) at col0 = p*16
__device__ __forceinline__ void rbf_row16(__half* dst, float t /*= d^2+eps*/) {
    float d = sqrtf(t);
    float f = __expf(-t * RBF_INVS2);      // f_0
    float r = __expf(d * RBF_K1 + RBF_K2); // ratio_0
    uint32_t pk[8];
#pragma unroll
    for (int m = 0; m < 8; m++) {
        float f0 = f; f *= r; r *= RBF_G;
        float f1 = f; f *= r; r *= RBF_G;
        __half2 h = __floats2half2_rn(f0, f1);
        pk[m] = *(uint32_t*)&h;
    }
    *(uint4*)(dst)     = make_uint4(pk[0], pk[1], pk[2], pk[3]);
    *(uint4*)(dst + 8) = make_uint4(pk[4], pk[5], pk[6], pk[7]);
}

// register-resident feature helpers (all indices compile-time)
#define DIRECT_FEAT(aa, da) do { \
    float v0 = ldd[(da)*3+0] - lx[0]; \
    float v1 = ldd[(da)*3+1] - lx[1]; \
    float v2 = ldd[(da)*3+2] - lx[2]; \
    float d0 = lq[0]*v0 + lq[1]*v1 + lq[2]*v2; \
    float d1 = lq[4]*v0 + lq[5]*v1 + lq[6]*v2; \
    float d2 = lq[8]*v0 + lq[9]*v1 + lq[10]*v2; \
    float nn = sqrtf(d0*d0 + d1*d1 + d2*d2); \
    if (nn == 0.0f) nn = 1.0f; \
    float iv = 1.0f / nn; \
    int k = 256 + (aa)*3; \
    Ah[e*KSE + k]     = __float2half_rn(d0 * iv); \
    Ah[e*KSE + k + 1] = __float2half_rn(d1 * iv); \
    Ah[e*KSE + k + 2] = __float2half_rn(d2 * iv); \
} while (0)

#define RBF_PAIR(p, a, b) do { \
    float dx = lx[(a)*3+0] - ldd[(b)*3+0]; \
    float dy = lx[(a)*3+1] - ldd[(b)*3+1]; \
    float dz = lx[(a)*3+2] - ldd[(b)*3+2]; \
    rbf_row16(Ah + e*KSE + ((p) << 4), dx*dx + dy*dy + dz*dz + 1e-6f); \
} while (0)

#define RBF_PAIRN(p, a, b) do { \
    float dx = lx[(a)*3+0] - lx[(b)*3+0]; \
    float dy = lx[(a)*3+1] - lx[(b)*3+1]; \
    float dz = lx[(a)*3+2] - lx[(b)*3+2]; \
    rbf_row16(Ah + e*KSE + ((p) << 4), dx*dx + dy*dy + dz*dz + 1e-6f); \
} while (0)

// ---------------- prep kernels ----------------
__global__ void wprepE_kernel(const float* __restrict__ eW) {
    int idx = blockIdx.x * 256 + threadIdx.x;
    if (idx >= 128 * KSE) return;
    int j = idx / KSE, k = idx - j * KSE;
    g_WE[idx] = __float2half_rn((k < 268) ? eW[j * 268 + k] : 0.0f);
}
__global__ void wprepN_kernel(const float* __restrict__ nW) {
    int idx = blockIdx.x * 256 + threadIdx.x;
    if (idx >= 128 * KSN) return;
    int j = idx / KSN, k = idx - j * KSN;
    g_WN[idx] = __float2half_rn((k < 96) ? nW[j * 96 + k] : 0.0f);
}
__global__ void q_kernel(const float* __restrict__ X, int N) {
    int n = blockIdx.x * blockDim.x + threadIdx.x;
    if (n >= N) return;
    float4* Qo = ((float4*)g_Q) + (size_t)n * 3;
    if (n == N - 1) {
        float4 z = make_float4(0.f, 0.f, 0.f, 0.f);
        Qo[0] = z; Qo[1] = z; Qo[2] = z;
        return;
    }
    const float* x = X + (size_t)n * 12;
    F3 X0 = {x[0], x[1], x[2]};
    F3 X1 = {x[3], x[4], x[5]};
    F3 X2 = {x[6], x[7], x[8]};
    F3 u0 = f3nrm(f3sub(X1, X0));
    F3 u1 = f3nrm(f3sub(X2, X1));
    F3 n0 = f3nrm(f3cross(u0, u1));
    F3 b1 = f3nrm(f3sub(u0, u1));
    F3 cc = f3cross(b1, n0);
    Qo[0] = make_float4(b1.x, n0.x, cc.x, 0.f);
    Qo[1] = make_float4(b1.y, n0.y, cc.y, 0.f);
    Qo[2] = make_float4(b1.z, n0.z, cc.z, 0.f);
}

// ---------------- MMA + quad-LN + store (R9-proven 1x8 warp tiling) ----------------
__device__ __forceinline__ void mma_ln_store(
    uint32_t aBase, uint32_t bBase, uint32_t bRowStepBytes, int S,
    int w, int lane,
    const float* sEB, const float* sGE, const float* sBE,
    float* __restrict__ outp, int rowbase, int rowlim)
{
    float acc[64];
#pragma unroll
    for (int i = 0; i < 64; i++) acc[i] = 0.f;

#pragma unroll 2
    for (int s = 0; s < S; s++) {
        uint32_t koff = (uint32_t)(s << 5);   // 16 halves = 32 bytes
        uint32_t a0, a1, a2, a3;
        ldsm4(a0, a1, a2, a3, aBase + koff);
#pragma unroll
        for (int np = 0; np < 8; np++) {
            uint32_t b0, b1, b2, b3;
            ldsm4(b0, b1, b2, b3, bBase + koff + (uint32_t)np * bRowStepBytes);
            MMA16816(&acc[(np*2    ) * 4], a0, a1, a2, a3, b0, b2);
            MMA16816(&acc[(np*2 + 1) * 4], a0, a1, a2, a3, b1, b3);
        }
    }

    // epilogue: bias + in-quad LayerNorm + store
    int rlo = lane >> 2, q = lane & 3;
#pragma unroll
    for (int h = 0; h < 2; h++) {
        float s1 = 0.f, s2 = 0.f;
#pragma unroll
        for (int nt = 0; nt < 16; nt++) {
            int j = nt * 8 + q * 2;
            float v0 = acc[nt*4 + h*2]     + sEB[j];
            float v1 = acc[nt*4 + h*2 + 1] + sEB[j + 1];
            acc[nt*4 + h*2]     = v0;
            acc[nt*4 + h*2 + 1] = v1;
            s1 += v0 + v1;
            s2 += v0*v0 + v1*v1;
        }
        s1 += __shfl_xor_sync(0xffffffffu, s1, 1);
        s2 += __shfl_xor_sync(0xffffffffu, s2, 1);
        s1 += __shfl_xor_sync(0xffffffffu, s1, 2);
        s2 += __shfl_xor_sync(0xffffffffu, s2, 2);
        float mean = s1 * (1.f/128.f);
        float var  = (s2 - s1 * mean) * (1.f/127.f);
        float inv  = 1.f / (sqrtf(var + 1e-6f) + 1e-6f);
        int row = rowbase + (w << 4) + rlo + h * 8;
        if (row < rowlim) {
            float* op = outp + (size_t)row * 128;
#pragma unroll
            for (int nt = 0; nt < 16; nt++) {
                int j = nt * 8 + q * 2;
                float2 ov;
                ov.x = sGE[j]     * (acc[nt*4 + h*2]     - mean) * inv + sBE[j];
                ov.y = sGE[j + 1] * (acc[nt*4 + h*2 + 1] - mean) * inv + sBE[j + 1];
                *(float2*)(op + j) = ov;
            }
        }
    }
}

// ---------------- fused persistent kernel with cross-tile gather prefetch ----------------
__global__ __launch_bounds__(ETHREADS, 1) void fused_kernel(
    const float* __restrict__ X,
    const int* __restrict__ inS, const int* __restrict__ inD,
    const int* __restrict__ exS, const int* __restrict__ exD,
    const float* __restrict__ nb_, const float* __restrict__ gn, const float* __restrict__ bn,
    const float* __restrict__ eb, const float* __restrict__ ge, const float* __restrict__ be,
    float* __restrict__ out, int N, int E)
{
    extern __shared__ char sm[];
    uint32_t smb = smem_u32(sm);
    int tid = threadIdx.x;
    int w = tid >> 5, lane = tid & 31;

    __half* Ah = (__half*)(sm + A_OFF);

    // one-time: weights + params into SMEM
    for (int i = tid; i < 128 * KSE / 8; i += ETHREADS)
        ((uint4*)(sm + WE_OFF))[i] = ((const uint4*)g_WE)[i];
    for (int i = tid; i < 128 * KSN / 8; i += ETHREADS)
        ((uint4*)(sm + WN_OFF))[i] = ((const uint4*)g_WN)[i];
    if (tid < 128) {
        ((float*)(sm + EB_OFF))[tid] = eb[tid];
        ((float*)(sm + GE_OFF))[tid] = ge[tid];
        ((float*)(sm + BE_OFF))[tid] = be[tid];
        ((float*)(sm + NB_OFF))[tid] = nb_[tid];
        ((float*)(sm + GN_OFF))[tid] = gn[tid];
        ((float*)(sm + BN_OFF))[tid] = bn[tid];
        *(unsigned long long*)(Ah + tid * KSE + 268) = 0ull;   // zero-pad k=268..271 once
    }
    __syncthreads();

    float* sXs = (float*)(sm + XS_OFF);
    float* sXd = (float*)(sm + XD_OFF);
    float* sQ  = (float*)(sm + Q_OFF);
    int*   sIdx = (int*)(sm + IDX_OFF);

    // ldmatrix lane address components (1x8 layout)
    int lm = lane >> 3, lr = lane & 7;
    uint32_t rowsel = (uint32_t)(((lm & 1) << 3) + lr);
    uint32_t colByte = (uint32_t)((lm >> 1) << 4);
    uint32_t aBase  = smb + A_OFF  + ((uint32_t)(w << 4) + rowsel) * (KSE * 2u) + colByte;
    uint32_t bBaseE = smb + WE_OFF + rowsel * (KSE * 2u) + colByte;
    uint32_t bBaseN = smb + WN_OFF + rowsel * (KSN * 2u) + colByte;

    float* outIn = out + (size_t)N * 128;
    float* outEx = outIn + (size_t)E * 128;

    int g = gridDim.x;
    int ntE = (E + 127) >> 7;
    int ntN = (N + 127) >> 7;
    int ntot = 2 * ntE + ntN;

    const float4* X4 = (const float4*)X;
    const float4* Q4 = (const float4*)g_Q;

    // prefetch state
    float4 pXs[2], pXd[2], pQ[2];
    int pIdx = 0;
    pXs[0] = pXs[1] = pXd[0] = pXd[1] = pQ[0] = pQ[1] = make_float4(0.f, 0.f, 0.f, 0.f);

    // ---------------- prologue: fill state for first tile ----------------
    int t0 = blockIdx.x;
    {
        if (t0 < 2 * ntE) {
            int set = (t0 >= ntE);
            int tl = set ? (t0 - ntE) : t0;
            const int* sp = set ? exS : inS;
            const int* dp = set ? exD : inD;
            int e = (tl << 7) + (tid & 127);
            if (e >= E) e = E - 1;
            pIdx = (tid < 128) ? sp[e] : dp[e];
        }
        sIdx[tid] = pIdx;
        __syncthreads();
        if (t0 < 2 * ntE) {
#pragma unroll
            for (int s2 = 0; s2 < 2; s2++) {
                int i = tid + (s2 << 8);
                if (i < 384) {
                    int e = i / 3, r = i - e * 3;
                    pXs[s2] = X4[(size_t)sIdx[e] * 3 + r];
                    pXd[s2] = X4[(size_t)sIdx[128 + e] * 3 + r];
                    pQ[s2]  = Q4[(size_t)sIdx[e] * 3 + r];
                }
            }
        } else {
            int b2 = (t0 - 2 * ntE) << 7;
#pragma unroll
            for (int s2 = 0; s2 < 2; s2++) {
                int i = tid + (s2 << 8);
                if (i < 384) {
                    int e = i / 3, r = i - e * 3;
                    int n = b2 + e; if (n >= N) n = N - 1;
                    pXs[s2] = X4[(size_t)n * 3 + r];
                }
            }
        }
        int tpp = t0 + g; if (tpp >= ntot) tpp = ntot - 1;
        if (tpp < 2 * ntE) {
            int set = (tpp >= ntE);
            int tl = set ? (tpp - ntE) : tpp;
            const int* sp = set ? exS : inS;
            const int* dp = set ? exD : inD;
            int e = (tl << 7) + (tid & 127);
            if (e >= E) e = E - 1;
            pIdx = (tid < 128) ? sp[e] : dp[e];
        }
        __syncthreads();
    }

    // ---------------- main loop ----------------
    for (int tcur = t0; tcur < ntot; tcur += g) {
        bool isE = (tcur < 2 * ntE);
        int base;
        float* outp;
        if (isE) {
            int set = (tcur >= ntE);
            int tl = set ? (tcur - ntE) : tcur;
            base = tl << 7;
            outp = set ? outEx : outIn;
        } else {
            base = (tcur - 2 * ntE) << 7;
            outp = out;
        }

        // ---- commit prefetched state (tile tcur gathers + idx(tcur+g)) ----
#pragma unroll
        for (int s2 = 0; s2 < 2; s2++) {
            int i = tid + (s2 << 8);
            if (i < 384) {
                ((float4*)sXs)[i] = pXs[s2];
                if (isE) {
                    ((float4*)sXd)[i] = pXd[s2];
                    ((float4*)sQ )[i] = pQ[s2];
                }
            }
        }
        sIdx[tid] = pIdx;
        __syncthreads();

        // ---- prefetch: gather(tcur+g) via sIdx, idx(tcur+2g) ----
        {
            int tn = tcur + g; if (tn >= ntot) tn = ntot - 1;
            if (tn < 2 * ntE) {
#pragma unroll
                for (int s2 = 0; s2 < 2; s2++) {
                    int i = tid + (s2 << 8);
                    if (i < 384) {
                        int e = i / 3, r = i - e * 3;
                        pXs[s2] = X4[(size_t)sIdx[e] * 3 + r];
                        pXd[s2] = X4[(size_t)sIdx[128 + e] * 3 + r];
                        pQ[s2]  = Q4[(size_t)sIdx[e] * 3 + r];
                    }
                }
            } else {
                int b2 = (tn - 2 * ntE) << 7;
#pragma unroll
                for (int s2 = 0; s2 < 2; s2++) {
                    int i = tid + (s2 << 8);
                    if (i < 384) {
                        int e = i / 3, r = i - e * 3;
                        int n = b2 + e; if (n >= N) n = N - 1;
                        pXs[s2] = X4[(size_t)n * 3 + r];
                    }
                }
            }
            int tpp = tcur + 2 * g; if (tpp >= ntot) tpp = ntot - 1;
            if (tpp < 2 * ntE) {
                int set2 = (tpp >= ntE);
                int tl2 = set2 ? (tpp - ntE) : tpp;
                const int* sp = set2 ? exS : inS;
                const int* dp = set2 ? exD : inD;
                int e = (tl2 << 7) + (tid & 127);
                if (e >= E) e = E - 1;
                pIdx = (tid < 128) ? sp[e] : dp[e];
            }
        }

        // ---- features: register-cached geometry, compile-time pair indices ----
        if (isE) {
            int e = tid & 127, hf = tid >> 7;
            float lx[12], ldd[12], lq[12];
            *(float4*)(lx)      = ((const float4*)sXs)[e*3 + 0];
            *(float4*)(lx + 4)  = ((const float4*)sXs)[e*3 + 1];
            *(float4*)(lx + 8)  = ((const float4*)sXs)[e*3 + 2];
            *(float4*)(ldd)     = ((const float4*)sXd)[e*3 + 0];
            *(float4*)(ldd + 4) = ((const float4*)sXd)[e*3 + 1];
            *(float4*)(ldd + 8) = ((const float4*)sXd)[e*3 + 2];
            *(float4*)(lq)      = ((const float4*)sQ)[e*3 + 0];
            *(float4*)(lq + 4)  = ((const float4*)sQ)[e*3 + 1];
            *(float4*)(lq + 8)  = ((const float4*)sQ)[e*3 + 2];

            if (hf == 0) {
                DIRECT_FEAT(0, 1);   // DSEL[0]=1
                DIRECT_FEAT(1, 0);   // DSEL[1]=0
                // pairs p=0..7: EPA={1,1,2,1,0,1,3,2}, EPB={1,2,1,0,1,3,1,2}
                RBF_PAIR(0, 1, 1);
                RBF_PAIR(1, 1, 2);
                RBF_PAIR(2, 2, 1);
                RBF_PAIR(3, 1, 0);
                RBF_PAIR(4, 0, 1);
                RBF_PAIR(5, 1, 3);
                RBF_PAIR(6, 3, 1);
                RBF_PAIR(7, 2, 2);
            } else {
                DIRECT_FEAT(2, 2);   // DSEL[2]=2
                DIRECT_FEAT(3, 3);   // DSEL[3]=3
                // pairs p=8..15: EPA={2,0,2,3,0,0,3,3}, EPB={0,2,3,2,0,3,0,3}
                RBF_PAIR(8,  2, 0);
                RBF_PAIR(9,  0, 2);
                RBF_PAIR(10, 2, 3);
                RBF_PAIR(11, 3, 2);
                RBF_PAIR(12, 0, 0);
                RBF_PAIR(13, 0, 3);
                RBF_PAIR(14, 3, 0);
                RBF_PAIR(15, 3, 3);
            }
            __syncthreads();

            mma_ln_store(aBase, bBaseE, (uint32_t)(16 * KSE * 2), 17, w, lane,
                         (const float*)(sm + EB_OFF), (const float*)(sm + GE_OFF), (const float*)(sm + BE_OFF),
                         outp, base, E);
        } else {
            int e = tid & 127, hf = tid >> 7;
            float lx[12];
            *(float4*)(lx)     = ((const float4*)sXs)[e*3 + 0];
            *(float4*)(lx + 4) = ((const float4*)sXs)[e*3 + 1];
            *(float4*)(lx + 8) = ((const float4*)sXs)[e*3 + 2];

            if (hf == 0) {
                // NPA/NPB pairs 0..2: (1,0) (1,2) (1,3)
                RBF_PAIRN(0, 1, 0);
                RBF_PAIRN(1, 1, 2);
                RBF_PAIRN(2, 1, 3);
            } else {
                // pairs 3..5: (0,2) (0,3) (3,2)
                RBF_PAIRN(3, 0, 2);
                RBF_PAIRN(4, 0, 3);
                RBF_PAIRN(5, 3, 2);
            }
            __syncthreads();

            mma_ln_store(aBase, bBaseN, (uint32_t)(16 * KSN * 2), 6, w, lane,
                         (const float*)(sm + NB_OFF), (const float*)(sm + GN_OFF), (const float*)(sm + BN_OFF),
                         out, base, N);
        }
    }
}

// ---------------- launch ----------------
extern "C" void kernel_launch(void* const* d_in, const int* in_sizes, int n_in,
                              void* d_out, int out_size)
{
    const float* X   = (const float*)d_in[0];
    const int*   Ein = (const int*)  d_in[1];
    const int*   Eex = (const int*)  d_in[2];
    const float* nW  = (const float*)d_in[3];
    const float* nb  = (const float*)d_in[4];
    const float* eW  = (const float*)d_in[5];
    const float* eb  = (const float*)d_in[6];
    const float* gn  = (const float*)d_in[7];
    const float* bn  = (const float*)d_in[8];
    const float* ge  = (const float*)d_in[9];
    const float* be  = (const float*)d_in[10];

    int N = in_sizes[0] / 12;
    int E = in_sizes[1] / 2;
    float* out = (float*)d_out;

    cudaFuncSetAttribute(fused_kernel, cudaFuncAttributeMaxDynamicSharedMemorySize, SMEM_T);

    wprepE_kernel<<<(128*KSE + 255)/256, 256>>>(eW);
    wprepN_kernel<<<(128*KSN + 255)/256, 256>>>(nW);
    q_kernel<<<(N + 255)/256, 256>>>(X, N);

    fused_kernel<<<EGRID, ETHREADS, SMEM_T>>>(
        X, Ein, Ein + E, Eex, Eex + E,
        nb, gn, bn, eb, ge, be, out, N, E);
}